// round 3
// baseline (speedup 1.0000x reference)
#include <cuda_runtime.h>

#define VOCAB 500
#define EMB   64
#define HID   64
#define BATCH 512
#define SEQ   512
#define NTOK  (BATCH * SEQ)

// Precomputed input projection: E'[v][i] = b_ih0[i] + sum_j emb[v][j]*W_ih0[i][j]
__device__ float g_xproj[VOCAB * HID];
// Converted (int64->int32 or passthrough) token indices, clamped to [0,VOCAB)
__device__ int g_idx[NTOK];

typedef unsigned long long u64;

__device__ __forceinline__ void fma2(u64 &d, u64 a, u64 b) {
    asm("fma.rn.f32x2 %0, %1, %2, %0;" : "+l"(d) : "l"(a), "l"(b));
}
__device__ __forceinline__ u64 add2(u64 a, u64 b) {
    u64 r; asm("add.rn.f32x2 %0, %1, %2;" : "=l"(r) : "l"(a), "l"(b)); return r;
}
__device__ __forceinline__ float2 unpack2(u64 v) {
    float2 r; asm("mov.b64 {%0,%1}, %2;" : "=f"(r.x), "=f"(r.y) : "l"(v)); return r;
}
__device__ __forceinline__ float fast_tanh(float x) {
    float e = __expf(2.0f * x);
    return 1.0f - __fdividef(2.0f, e + 1.0f);
}

// ---------------------------------------------------------------------------
// Kernel 0: detect index dtype (int64 vs int32) and convert to int32.
// If int64 (little-endian), every odd 32-bit word of the first 128 is zero.
// ---------------------------------------------------------------------------
__global__ void convert_idx_kernel(const int* __restrict__ xw) {
    __shared__ int s_is64;
    if (threadIdx.x == 0) {
        int z = 0;
        #pragma unroll
        for (int k = 1; k < 128; k += 2) z |= xw[k];
        s_is64 = (z == 0);
    }
    __syncthreads();
    const int is64 = s_is64;
    int k = blockIdx.x * blockDim.x + threadIdx.x;
    if (k < NTOK) {
        int v = is64 ? xw[2 * k] : xw[k];
        v = min(max(v, 0), VOCAB - 1);   // safety clamp: never OOB
        g_idx[k] = v;
    }
}

// ---------------------------------------------------------------------------
// Kernel 1: fold embedding + layer-0 input projection into a 500x64 LUT.
// ---------------------------------------------------------------------------
__global__ void xproj_kernel(const float* __restrict__ emb,
                             const float* __restrict__ W_ih0,
                             const float* __restrict__ b_ih0) {
    __shared__ float se[EMB];
    const int v = blockIdx.x;
    const int i = threadIdx.x;
    se[i] = emb[v * EMB + i];
    __syncthreads();
    float acc = 0.0f;
    const float4* wr = (const float4*)(W_ih0 + i * EMB);
    #pragma unroll
    for (int q = 0; q < 16; q++) {
        float4 wv = __ldg(wr + q);
        acc += wv.x * se[4*q+0] + wv.y * se[4*q+1] + wv.z * se[4*q+2] + wv.w * se[4*q+3];
    }
    g_xproj[v * HID + i] = acc + b_ih0[i];
}

// ---------------------------------------------------------------------------
// Kernel 2: per-row sequential scan. One CTA (128 threads, 4 warps) per batch
// row. Warp w owns outputs i in [16w, 16w+16). Within a lane pair, lane&1
// selects the j-half [32*(lane&1), +32). Weights live in 48 u64 regs/thread.
// j-reduction = one shfl_xor(1). Hidden state double-buffered in smem with
// the upper half at float offset 36 so even/odd lane groups hit disjoint
// banks (conflict-free 128-bit LDS). 2 barriers per step.
// ---------------------------------------------------------------------------
__global__ void __launch_bounds__(128, 4)
scan_kernel(const float* __restrict__ W_hh0,
            const float* __restrict__ b_hh0,
            const float* __restrict__ W_ih1,
            const float* __restrict__ W_hh1,
            const float* __restrict__ b_ih1,
            const float* __restrict__ b_hh1,
            const float* __restrict__ fc_w,
            const float* __restrict__ fc_b,
            float* __restrict__ out) {
    __shared__ __align__(16) float sb1[2][68];   // h1 double-buffered, padded
    __shared__ __align__(16) float sb2[2][68];   // h2 double-buffered, padded
    __shared__ int   sidx[SEQ];
    __shared__ float swsum[4];

    const int tid  = threadIdx.x;
    const int w    = tid >> 5;
    const int lane = tid & 31;
    const int pair = lane >> 1;      // 0..15
    const int jh   = lane & 1;       // j-half selector
    const int i    = w * 16 + pair;  // owned output row, 0..63
    const int jbase = jh * 32;
    const int hoff  = jh * 36;       // padded upper-half offset (16B aligned)
    const int iw    = (i < 32) ? i : i + 4;  // padded write index

    // --- weights: 1 row x 32 j per matrix, as f32x2 pairs (96 regs) ---
    u64 whh0[16], whh1[16], wih1[16];
    {
        const u64* q0 = (const u64*)(W_hh0 + i * HID + jbase);
        const u64* q1 = (const u64*)(W_hh1 + i * HID + jbase);
        const u64* q2 = (const u64*)(W_ih1 + i * HID + jbase);
        #pragma unroll
        for (int q = 0; q < 16; q++) {
            whh0[q] = __ldg(q0 + q);
            whh1[q] = __ldg(q1 + q);
            wih1[q] = __ldg(q2 + q);
        }
    }
    const float bias1 = b_hh0[i];
    const float bias2 = b_ih1[i] + b_hh1[i];

    // --- stage indices, zero h buffers ---
    const int b = blockIdx.x;
    const int* xr = g_idx + b * SEQ;
    #pragma unroll
    for (int k = tid; k < SEQ; k += 128) sidx[k] = xr[k];
    if (tid < 68) {
        sb1[0][tid] = 0.0f; sb1[1][tid] = 0.0f;
        sb2[0][tid] = 0.0f; sb2[1][tid] = 0.0f;
    }
    __syncthreads();

    float xn = __ldg(&g_xproj[sidx[0] * HID + i]);  // prefetch step-0 input
    float h2n = 0.0f;

    for (int t = 0; t < SEQ; t++) {
        const int cur = t & 1, nxt = cur ^ 1;
        const float xcur = xn;
        if (t + 1 < SEQ) xn = __ldg(&g_xproj[sidx[t + 1] * HID + i]);

        // --- stage A: p1 = Whh0*h1_old, p2 = Whh1*h2_old (own 32 j's) ---
        const ulonglong2* ph1 = (const ulonglong2*)(sb1[cur] + hoff);
        const ulonglong2* ph2 = (const ulonglong2*)(sb2[cur] + hoff);
        u64 a0 = 0, a1 = 0, c0 = 0, c1 = 0;
        #pragma unroll
        for (int m = 0; m < 8; m++) {
            ulonglong2 hv = ph1[m];
            fma2(a0, whh0[2*m],   hv.x);
            fma2(a1, whh0[2*m+1], hv.y);
            ulonglong2 gv = ph2[m];
            fma2(c0, whh1[2*m],   gv.x);
            fma2(c1, whh1[2*m+1], gv.y);
        }
        float2 fa = unpack2(add2(a0, a1));
        float p1 = fa.x + fa.y;
        p1 += __shfl_xor_sync(0xffffffffu, p1, 1);
        float2 fc = unpack2(add2(c0, c1));
        float p2 = fc.x + fc.y;
        p2 += __shfl_xor_sync(0xffffffffu, p2, 1);

        const float h1n = fast_tanh(p1 + xcur + bias1);
        if (jh == 0) sb1[nxt][iw] = h1n;
        __syncthreads();  // B1: h1_new visible

        // --- stage B: p3 = Wih1*h1_new ---
        const ulonglong2* ph1n = (const ulonglong2*)(sb1[nxt] + hoff);
        u64 d0 = 0, d1 = 0, d2 = 0, d3 = 0;
        #pragma unroll
        for (int m = 0; m < 8; m += 2) {
            ulonglong2 hv = ph1n[m];
            fma2(d0, wih1[2*m],   hv.x);
            fma2(d1, wih1[2*m+1], hv.y);
            ulonglong2 hw = ph1n[m+1];
            fma2(d2, wih1[2*m+2], hw.x);
            fma2(d3, wih1[2*m+3], hw.y);
        }
        float2 fd = unpack2(add2(add2(d0, d1), add2(d2, d3)));
        float p3 = fd.x + fd.y;
        p3 += __shfl_xor_sync(0xffffffffu, p3, 1);

        h2n = fast_tanh(p3 + p2 + bias2);
        if (jh == 0) sb2[nxt][iw] = h2n;
        __syncthreads();  // B2: h2_new visible
    }

    // --- final projection: out[b] = fc_w . h2 + fc_b ---
    float val = (jh == 0) ? __ldg(&fc_w[i]) * h2n : 0.0f;
    #pragma unroll
    for (int off = 16; off; off >>= 1)
        val += __shfl_xor_sync(0xffffffffu, val, off);
    if (lane == 0) swsum[w] = val;
    __syncthreads();
    if (tid == 0) out[b] = swsum[0] + swsum[1] + swsum[2] + swsum[3] + fc_b[0];
}

// ---------------------------------------------------------------------------
extern "C" void kernel_launch(void* const* d_in, const int* in_sizes, int n_in,
                              void* d_out, int out_size) {
    const int*   x_raw = (const int*)d_in[0];
    const float* emb   = (const float*)d_in[1];
    const float* W_ih0 = (const float*)d_in[2];
    const float* W_hh0 = (const float*)d_in[3];
    const float* b_ih0 = (const float*)d_in[4];
    const float* b_hh0 = (const float*)d_in[5];
    const float* W_ih1 = (const float*)d_in[6];
    const float* W_hh1 = (const float*)d_in[7];
    const float* b_ih1 = (const float*)d_in[8];
    const float* b_hh1 = (const float*)d_in[9];
    const float* fc_w  = (const float*)d_in[10];
    const float* fc_b  = (const float*)d_in[11];
    float*       out   = (float*)d_out;

    convert_idx_kernel<<<(NTOK + 255) / 256, 256>>>(x_raw);
    xproj_kernel<<<VOCAB, HID>>>(emb, W_ih0, b_ih0);
    scan_kernel<<<BATCH, 128>>>(W_hh0, b_hh0, W_ih1, W_hh1, b_ih1, b_hh1,
                                fc_w, fc_b, out);
}

// round 4
// speedup vs baseline: 1.2618x; 1.2618x over previous
#include <cuda_runtime.h>

#define VOCAB 500
#define EMB   64
#define HID   64
#define BATCH 512
#define SEQ   512
#define NTOK  (BATCH * SEQ)
#define ROWS_PER_CTA 4

// Precomputed input projection: E'[v][i] = b_ih0[i] + sum_j emb[v][j]*W_ih0[i][j]
__device__ float g_xproj[VOCAB * HID];
// Converted (int64->int32 or passthrough) token indices, clamped to [0,VOCAB)
__device__ int g_idx[NTOK];

typedef unsigned long long u64;

__device__ __forceinline__ void fma2(u64 &d, u64 a, u64 b) {
    asm("fma.rn.f32x2 %0, %1, %2, %0;" : "+l"(d) : "l"(a), "l"(b));
}
__device__ __forceinline__ u64 add2(u64 a, u64 b) {
    u64 r; asm("add.rn.f32x2 %0, %1, %2;" : "=l"(r) : "l"(a), "l"(b)); return r;
}
__device__ __forceinline__ float hsum2(u64 a, u64 b) {
    u64 s = add2(a, b);
    float lo, hi;
    asm("mov.b64 {%0,%1}, %2;" : "=f"(lo), "=f"(hi) : "l"(s));
    return lo + hi;
}
__device__ __forceinline__ float fast_tanh(float x) {
    float e = __expf(2.0f * x);
    return 1.0f - __fdividef(2.0f, e + 1.0f);
}

// ---------------------------------------------------------------------------
// Kernel 0: detect index dtype (int64 vs int32) and convert to int32.
// If int64 (little-endian), every odd 32-bit word of the first 128 is zero.
// ---------------------------------------------------------------------------
__global__ void convert_idx_kernel(const int* __restrict__ xw) {
    __shared__ int s_is64;
    if (threadIdx.x == 0) {
        int z = 0;
        #pragma unroll
        for (int k = 1; k < 128; k += 2) z |= xw[k];
        s_is64 = (z == 0);
    }
    __syncthreads();
    const int is64 = s_is64;
    int k = blockIdx.x * blockDim.x + threadIdx.x;
    if (k < NTOK) {
        int v = is64 ? xw[2 * k] : xw[k];
        v = min(max(v, 0), VOCAB - 1);   // safety clamp: never OOB
        g_idx[k] = v;
    }
}

// ---------------------------------------------------------------------------
// Kernel 1: fold embedding + layer-0 input projection into a 500x64 LUT.
// ---------------------------------------------------------------------------
__global__ void xproj_kernel(const float* __restrict__ emb,
                             const float* __restrict__ W_ih0,
                             const float* __restrict__ b_ih0) {
    __shared__ float se[EMB];
    const int v = blockIdx.x;
    const int i = threadIdx.x;
    se[i] = emb[v * EMB + i];
    __syncthreads();
    float acc = 0.0f;
    const float4* wr = (const float4*)(W_ih0 + i * EMB);
    #pragma unroll
    for (int q = 0; q < 16; q++) {
        float4 wv = __ldg(wr + q);
        acc += wv.x * se[4*q+0] + wv.y * se[4*q+1] + wv.z * se[4*q+2] + wv.w * se[4*q+3];
    }
    g_xproj[v * HID + i] = acc + b_ih0[i];
}

// ---------------------------------------------------------------------------
// Kernel 2: sequential scan. CTA = 256 threads = 4 batch rows (64 thr/row),
// grid = 128 -> exactly 1 CTA/SM, 8 warps filling all 4 SMSPs (2 each).
// Thread owns output i of its row with the FULL j range: no shfl, no partial
// exchange, 2 tanh/thread/step, 2 barriers/step. Weights: 3x64 floats = 192
// regs as f32x2 pairs. After h1_new is published, BOTH Wih1*h1 (this step)
// and Whh0*h1 (next step's recurrent term) are computed from one set of
// 16 LDS.128 loads. h buffers are single-buffered (barriers order reuse).
// ---------------------------------------------------------------------------
__global__ void __launch_bounds__(64 * ROWS_PER_CTA, 1)
scan_kernel(const float* __restrict__ W_hh0,
            const float* __restrict__ b_hh0,
            const float* __restrict__ W_ih1,
            const float* __restrict__ W_hh1,
            const float* __restrict__ b_ih1,
            const float* __restrict__ b_hh1,
            const float* __restrict__ fc_w,
            const float* __restrict__ fc_b,
            float* __restrict__ out) {
    __shared__ __align__(16) float sh1[ROWS_PER_CTA][HID];
    __shared__ __align__(16) float sh2[ROWS_PER_CTA][HID];
    __shared__ int   sidx[ROWS_PER_CTA][SEQ];
    __shared__ float swsum[ROWS_PER_CTA][2];

    const int tid  = threadIdx.x;
    const int row  = tid >> 6;          // 0..3  (2 warps per row)
    const int i    = tid & 63;          // owned output
    const int lane = tid & 31;
    const int half = (tid >> 5) & 1;    // which warp of the row
    const int b    = blockIdx.x * ROWS_PER_CTA + row;

    // --- weights: full row i of each matrix, as f32x2 pairs (192 regs) ---
    u64 w0[32], w1[32], w2[32];         // W_hh0, W_ih1, W_hh1
    {
        const u64* q0 = (const u64*)(W_hh0 + i * HID);
        const u64* q1 = (const u64*)(W_ih1 + i * HID);
        const u64* q2 = (const u64*)(W_hh1 + i * HID);
        #pragma unroll
        for (int q = 0; q < 32; q++) {
            w0[q] = __ldg(q0 + q);
            w1[q] = __ldg(q1 + q);
            w2[q] = __ldg(q2 + q);
        }
    }
    const float b1 = b_hh0[i];
    const float b2 = b_ih1[i] + b_hh1[i];

    // --- stage this row's indices into smem ---
    const int* xr = g_idx + b * SEQ;
    #pragma unroll
    for (int k = i; k < SEQ; k += 64) sidx[row][k] = xr[k];
    __syncthreads();

    float*      my_h1 = sh1[row];
    float*      my_h2 = sh2[row];
    const int*  my_ix = sidx[row];

    // carried recurrent terms (h[-1] = 0)
    float c_q = 0.0f;                       // Whh0 . h1_prev
    float c_r = 0.0f;                       // Whh1 . h2_prev
    float xn  = __ldg(&g_xproj[my_ix[0] * HID + i]);
    float h2n = 0.0f;

    #pragma unroll 1
    for (int t = 0; t < SEQ; t++) {
        const float xc = xn;
        const int tn = (t + 1 < SEQ) ? (t + 1) : (SEQ - 1);
        xn = __ldg(&g_xproj[my_ix[tn] * HID + i]);   // prefetch next input

        // h1_new = tanh(Whh0.h1_prev + x_t + b1)
        const float h1n = fast_tanh(c_q + xc + b1);
        my_h1[i] = h1n;
        __syncthreads();   // B1: h1_new visible

        // one pass over h1_new feeds BOTH Wih1 (this step) and Whh0 (next)
        const ulonglong2* H1 = (const ulonglong2*)my_h1;
        u64 s0 = 0, s1 = 0, q0 = 0, q1v = 0;
        #pragma unroll
        for (int m = 0; m < 16; m++) {
            ulonglong2 hv = H1[m];
            fma2(s0,  w1[2*m],   hv.x);
            fma2(s1,  w1[2*m+1], hv.y);
            fma2(q0,  w0[2*m],   hv.x);
            fma2(q1v, w0[2*m+1], hv.y);
        }
        const float s = hsum2(s0, s1);
        c_q = hsum2(q0, q1v);

        // h2_new = tanh(Wih1.h1_new + Whh1.h2_prev + b2)
        h2n = fast_tanh(s + c_r + b2);
        my_h2[i] = h2n;
        __syncthreads();   // B2: h2_new visible

        // recurrent term for next step: Whh1 . h2_new
        const ulonglong2* H2 = (const ulonglong2*)my_h2;
        u64 r0 = 0, r1 = 0;
        #pragma unroll
        for (int m = 0; m < 16; m++) {
            ulonglong2 gv = H2[m];
            fma2(r0, w2[2*m],   gv.x);
            fma2(r1, w2[2*m+1], gv.y);
        }
        c_r = hsum2(r0, r1);
    }

    // --- final projection: out[b] = fc_w . h2 + fc_b ---
    float val = __ldg(&fc_w[i]) * h2n;
    #pragma unroll
    for (int off = 16; off; off >>= 1)
        val += __shfl_xor_sync(0xffffffffu, val, off);
    if (lane == 0) swsum[row][half] = val;
    __syncthreads();
    if (i == 0) out[b] = swsum[row][0] + swsum[row][1] + fc_b[0];
}

// ---------------------------------------------------------------------------
extern "C" void kernel_launch(void* const* d_in, const int* in_sizes, int n_in,
                              void* d_out, int out_size) {
    const int*   x_raw = (const int*)d_in[0];
    const float* emb   = (const float*)d_in[1];
    const float* W_ih0 = (const float*)d_in[2];
    const float* W_hh0 = (const float*)d_in[3];
    const float* b_ih0 = (const float*)d_in[4];
    const float* b_hh0 = (const float*)d_in[5];
    const float* W_ih1 = (const float*)d_in[6];
    const float* W_hh1 = (const float*)d_in[7];
    const float* b_ih1 = (const float*)d_in[8];
    const float* b_hh1 = (const float*)d_in[9];
    const float* fc_w  = (const float*)d_in[10];
    const float* fc_b  = (const float*)d_in[11];
    float*       out   = (float*)d_out;

    convert_idx_kernel<<<(NTOK + 255) / 256, 256>>>(x_raw);
    xproj_kernel<<<VOCAB, HID>>>(emb, W_ih0, b_ih0);
    scan_kernel<<<BATCH / ROWS_PER_CTA, 64 * ROWS_PER_CTA>>>(
        W_hh0, b_hh0, W_ih1, W_hh1, b_ih1, b_hh1, fc_w, fc_b, out);
}